// round 12
// baseline (speedup 1.0000x reference)
#include <cuda_runtime.h>
#include <cuda_bf16.h>
#include <cstdint>
#include <cfloat>

// Router: alpha = softmax(topk_mask(z @ W^T + b))
// z:[8192,4096]f32  W:[64,4096]f32  b:[64]f32  k=2
// K1: single-pass bf16 GEMM (approx logits, used ONLY to pick candidates).
// K2: per-row top-6 candidates -> exact fp32 dots (z re-read) -> top-k+softmax.

namespace {
typedef uint32_t u32;
typedef unsigned long long ull;
constexpr int D = 4096;
constexpr int Kc = 64;
constexpr int NROWS = 8192;
constexpr int BM = 64;
constexpr int BK = 128;
constexpr int NSTG = D / BK;         // 32
constexpr int NT1 = 512;             // 16 warps

constexpr int ROWB = 272;            // 128 bf16 + 16B pad; ldsm conflict-free
constexpr int B_OFF = 64 * ROWB;     // 17408
constexpr int STG_B = 2 * B_OFF;     // 34816
constexpr int SMEM1 = 3 * STG_B;     // 104448 dynamic

__device__ float g_logits[NROWS * Kc];   // 2MB approx logits (+bias)

__device__ __forceinline__ void mma_bf16(float* d, const u32* a, u32 b0, u32 b1) {
    asm volatile(
        "mma.sync.aligned.m16n8k16.row.col.f32.bf16.bf16.f32 "
        "{%0,%1,%2,%3}, {%4,%5,%6,%7}, {%8,%9}, {%0,%1,%2,%3};"
        : "+f"(d[0]), "+f"(d[1]), "+f"(d[2]), "+f"(d[3])
        : "r"(a[0]), "r"(a[1]), "r"(a[2]), "r"(a[3]), "r"(b0), "r"(b1));
}
__device__ __forceinline__ void ldsm4(u32* r, u32 addr) {
    asm volatile(
        "ldmatrix.sync.aligned.m8n8.x4.shared.b16 {%0,%1,%2,%3}, [%4];"
        : "=r"(r[0]), "=r"(r[1]), "=r"(r[2]), "=r"(r[3]) : "r"(addr));
}
__device__ __forceinline__ u32 smem_u32(const void* p) {
    u32 a;
    asm("{ .reg .u64 t; cvta.to.shared.u64 t, %1; cvt.u32.u64 %0, t; }"
        : "=r"(a) : "l"(p));
    return a;
}
// pack: low half <- bf16(x), high half <- bf16(y)  (memory order x,y)
__device__ __forceinline__ u32 pbf2(float x, float y) {
    u32 r;
    asm("cvt.rn.bf16x2.f32 %0, %1, %2;" : "=r"(r) : "f"(y), "f"(x));
    return r;
}
__device__ __forceinline__ uint4 pack8(float4 a, float4 c) {
    uint4 r;
    r.x = pbf2(a.x, a.y); r.y = pbf2(a.z, a.w);
    r.z = pbf2(c.x, c.y); r.w = pbf2(c.z, c.w);
    return r;
}
// packed dual-fma f32x2
__device__ __forceinline__ void ffma2(ull& d, ull a, ull b) {
    asm("fma.rn.f32x2 %0, %1, %2, %3;" : "=l"(d) : "l"(a), "l"(b), "l"(d));
}
__device__ __forceinline__ float2 upk2(ull v) {
    float2 r;
    asm("mov.b64 {%0, %1}, %2;" : "=f"(r.x), "=f"(r.y) : "l"(v));
    return r;
}
} // namespace

extern __shared__ __align__(16) char smem1[];

// ---------------- K1: bf16 approx GEMM ----------------
__global__ __launch_bounds__(NT1, 1) void router_gemm_kernel(
    const float* __restrict__ z, const float* __restrict__ W,
    const float* __restrict__ b)
{
    const int tid = threadIdx.x;
    const int wid = tid >> 5;
    const int lane = tid & 31;
    const int row0 = blockIdx.x * BM;

    // producer: thread owns 16 contiguous k of one z row + one W row
    const int pr = tid >> 3;             // 0..63
    const int kq = (tid & 7) * 16;       // 0..112
    const float* zg = z + (size_t)(row0 + pr) * D + kq;
    const float* wg = W + (size_t)pr * D + kq;
    const int stsA = pr * ROWB + kq * 2;
    const int stsB = B_OFF + stsA;

    // consumer: warp (mw 0..3 m16-slab, nw 0..3 n16-block)
    const int mw = wid & 3;
    const int nw = wid >> 2;
    const u32 sb = smem_u32(smem1);
    const u32 aB = sb + (u32)((mw * 16 + (lane & 15)) * ROWB + (lane >> 4) * 16);
    const u32 bB = sb + (u32)(B_OFF + (nw * 16 + (lane & 7) + ((lane >> 4) << 3)) * ROWB
                              + (((lane >> 3) & 1) * 16));

    float acc[2][4];
#pragma unroll
    for (int j = 0; j < 2; ++j)
#pragma unroll
        for (int q = 0; q < 4; ++q) acc[j][q] = 0.f;

    float4 zv0, zv1, zv2, zv3, wv0, wv1, wv2, wv3;

#define LDG_STAGE(t)                                   \
    do {                                               \
        const float* zp = zg + (t) * BK;               \
        const float* wp = wg + (t) * BK;               \
        zv0 = *(const float4*)(zp);                    \
        zv1 = *(const float4*)(zp + 4);                \
        zv2 = *(const float4*)(zp + 8);                \
        zv3 = *(const float4*)(zp + 12);               \
        wv0 = *(const float4*)(wp);                    \
        wv1 = *(const float4*)(wp + 4);                \
        wv2 = *(const float4*)(wp + 8);                \
        wv3 = *(const float4*)(wp + 12);               \
    } while (0)

#define STS_STAGE(buf)                                 \
    do {                                               \
        char* s_ = smem1 + (buf) * STG_B;              \
        *(uint4*)(s_ + stsA)      = pack8(zv0, zv1);   \
        *(uint4*)(s_ + stsA + 16) = pack8(zv2, zv3);   \
        *(uint4*)(s_ + stsB)      = pack8(wv0, wv1);   \
        *(uint4*)(s_ + stsB + 16) = pack8(wv2, wv3);   \
    } while (0)

    LDG_STAGE(0);
    STS_STAGE(0);
    LDG_STAGE(1);
    STS_STAGE(1);
    LDG_STAGE(2);
    __syncthreads();

#pragma unroll
    for (int t = 0; t < NSTG; ++t) {
        const u32 so = (u32)((t % 3) * STG_B);
#pragma unroll
        for (int kc = 0; kc < 8; ++kc) {
            const u32 ko = kc * 32;  // 16 bf16
            u32 ar[4], br[4];
            ldsm4(ar, aB + so + ko);
            ldsm4(br, bB + so + ko);
            mma_bf16(acc[0], ar, br[0], br[1]);
            mma_bf16(acc[1], ar, br[2], br[3]);
        }
        if (t + 2 < NSTG) STS_STAGE((t + 2) % 3);
        if (t + 3 < NSTG) LDG_STAGE(t + 3);
        __syncthreads();
    }

    // write approx logits (+bias)
    const int rr = lane >> 2;
    const int cc = (lane & 3) * 2;
    const int row = row0 + mw * 16 + rr;
#pragma unroll
    for (int nb = 0; nb < 2; ++nb) {
        const int col = nw * 16 + nb * 8 + cc;
        *(float2*)(g_logits + (size_t)row * Kc + col) =
            make_float2(acc[nb][0] + b[col], acc[nb][1] + b[col + 1]);
        *(float2*)(g_logits + (size_t)(row + 8) * Kc + col) =
            make_float2(acc[nb][2] + b[col], acc[nb][3] + b[col + 1]);
    }
#undef LDG_STAGE
#undef STS_STAGE
}

// ---------------- K2: candidate refine + top-k + softmax ----------------
__global__ __launch_bounds__(256, 4) void router_refine_kernel(
    const float* __restrict__ z, const float* __restrict__ W,
    const float* __restrict__ b, const int* __restrict__ kptr,
    float* __restrict__ out)
{
    __shared__ float s_e[8][Kc];  // generic path only

    const int wid = threadIdx.x >> 5;
    const int lane = threadIdx.x & 31;
    const int row = blockIdx.x * 8 + wid;
    const int c0 = lane * 2;

    int kk = kptr ? *kptr : 2;
    if (kk < 1) kk = 1;
    if (kk > Kc) kk = Kc;

    const float* zr = z + (size_t)row * D;
    const size_t zoff = (size_t)lane * 4;  // float4 per lane per chunk

    if (kk == 2) {
        const float2 lg = *(const float2*)(g_logits + (size_t)row * Kc + c0);
        const float l0 = lg.x, l1 = lg.y;

        // ---- top-6 candidate selection from approx logits ----
        int cand[6];
        unsigned sel = 0;
#pragma unroll
        for (int p = 0; p < 6; ++p) {
            float bv = (sel & 1) ? -FLT_MAX : l0;
            int bi = c0;
            const float c1v = (sel & 2) ? -FLT_MAX : l1;
            if (c1v > bv) { bv = c1v; bi = c0 + 1; }
#pragma unroll
            for (int off = 16; off; off >>= 1) {
                const float ov = __shfl_xor_sync(0xffffffffu, bv, off);
                const int oi = __shfl_xor_sync(0xffffffffu, bi, off);
                if (ov > bv || (ov == bv && oi < bi)) { bv = ov; bi = oi; }
            }
            cand[p] = bi;
            if ((bi >> 1) == lane) sel |= 1u << (bi & 1);
        }

        // ---- exact fp32 dots for the 6 candidates ----
        const float* wp0 = W + (size_t)cand[0] * D;
        const float* wp1 = W + (size_t)cand[1] * D;
        const float* wp2 = W + (size_t)cand[2] * D;
        const float* wp3 = W + (size_t)cand[3] * D;
        const float* wp4 = W + (size_t)cand[4] * D;
        const float* wp5 = W + (size_t)cand[5] * D;

        ull a0[6], a1[6];
#pragma unroll
        for (int j = 0; j < 6; ++j) { a0[j] = 0ull; a1[j] = 0ull; }

#pragma unroll 4
        for (int it = 0; it < D / 128; ++it) {
            const size_t o = (size_t)it * 128 + zoff;
            const ulonglong2 zv = *(const ulonglong2*)(zr + o);
            ulonglong2 wv;
            wv = *(const ulonglong2*)(wp0 + o); ffma2(a0[0], zv.x, wv.x); ffma2(a1[0], zv.y, wv.y);
            wv = *(const ulonglong2*)(wp1 + o); ffma2(a0[1], zv.x, wv.x); ffma2(a1[1], zv.y, wv.y);
            wv = *(const ulonglong2*)(wp2 + o); ffma2(a0[2], zv.x, wv.x); ffma2(a1[2], zv.y, wv.y);
            wv = *(const ulonglong2*)(wp3 + o); ffma2(a0[3], zv.x, wv.x); ffma2(a1[3], zv.y, wv.y);
            wv = *(const ulonglong2*)(wp4 + o); ffma2(a0[4], zv.x, wv.x); ffma2(a1[4], zv.y, wv.y);
            wv = *(const ulonglong2*)(wp5 + o); ffma2(a0[5], zv.x, wv.x); ffma2(a1[5], zv.y, wv.y);
        }

        float e[6];
#pragma unroll
        for (int j = 0; j < 6; ++j) {
            const float2 u = upk2(a0[j]);
            const float2 v = upk2(a1[j]);
            float s = (u.x + u.y) + (v.x + v.y);
#pragma unroll
            for (int off = 16; off; off >>= 1)
                s += __shfl_xor_sync(0xffffffffu, s, off);
            e[j] = s + b[cand[j]];
        }

        // ---- exact top-2 among candidates (val desc, idx asc) ----
        float hv = -FLT_MAX, lv = -FLT_MAX;
        int hi_ = 1 << 30, li_ = 1 << 30;
#pragma unroll
        for (int j = 0; j < 6; ++j) {
            const float v = e[j];
            const int i = cand[j];
            if (v > hv || (v == hv && i < hi_)) {
                lv = hv; li_ = hi_;
                hv = v; hi_ = i;
            } else if (v > lv || (v == lv && i < li_)) {
                lv = v; li_ = i;
            }
        }
        const float elo = expf(lv - hv);
        const float inv = 1.0f / (1.0f + elo);
        const float eli = elo * inv;
        const float o0 = (c0 == hi_) ? inv : ((c0 == li_) ? eli : 0.f);
        const float o1 = (c0 + 1 == hi_) ? inv : ((c0 + 1 == li_) ? eli : 0.f);
        *(float2*)(out + (size_t)row * Kc + c0) = make_float2(o0, o1);
        return;
    }

    // ---- generic k path: compute ALL 64 exact logits, then top-k+softmax ----
    for (int base = 0; base < Kc; base += 8) {
        ull a0[8], a1[8];
#pragma unroll
        for (int j = 0; j < 8; ++j) { a0[j] = 0ull; a1[j] = 0ull; }
        for (int it = 0; it < D / 128; ++it) {
            const size_t o = (size_t)it * 128 + zoff;
            const ulonglong2 zv = *(const ulonglong2*)(zr + o);
#pragma unroll
            for (int j = 0; j < 8; ++j) {
                const ulonglong2 wv =
                    *(const ulonglong2*)(W + (size_t)(base + j) * D + o);
                ffma2(a0[j], zv.x, wv.x);
                ffma2(a1[j], zv.y, wv.y);
            }
        }
#pragma unroll
        for (int j = 0; j < 8; ++j) {
            const float2 u = upk2(a0[j]);
            const float2 v = upk2(a1[j]);
            float s = (u.x + u.y) + (v.x + v.y);
#pragma unroll
            for (int off = 16; off; off >>= 1)
                s += __shfl_xor_sync(0xffffffffu, s, off);
            if (lane == 0) s_e[wid][base + j] = s + b[base + j];
        }
    }
    __syncwarp();

    const float v0 = s_e[wid][c0];
    const float v1 = s_e[wid][c0 + 1];
    unsigned sel = 0;
    float m = 0.f;
    for (int p = 0; p < kk; ++p) {
        float bv = (sel & 1) ? -FLT_MAX : v0;
        int bi = c0;
        const float c1v = (sel & 2) ? -FLT_MAX : v1;
        if (c1v > bv) { bv = c1v; bi = c0 + 1; }
#pragma unroll
        for (int off = 16; off; off >>= 1) {
            const float ov = __shfl_xor_sync(0xffffffffu, bv, off);
            const int oi = __shfl_xor_sync(0xffffffffu, bi, off);
            if (ov > bv || (ov == bv && oi < bi)) { bv = ov; bi = oi; }
        }
        if (p == 0) m = bv;
        if ((bi >> 1) == lane) sel |= 1u << (bi & 1);
    }
    const float e0 = (sel & 1) ? expf(v0 - m) : 0.f;
    const float e1 = (sel & 2) ? expf(v1 - m) : 0.f;
    float s = e0 + e1;
#pragma unroll
    for (int off = 16; off; off >>= 1) s += __shfl_xor_sync(0xffffffffu, s, off);
    const float inv = 1.0f / s;
    *(float2*)(out + (size_t)row * Kc + c0) = make_float2(e0 * inv, e1 * inv);
}

extern "C" void kernel_launch(void* const* d_in, const int* in_sizes, int n_in,
                              void* d_out, int out_size) {
    const float* z = (const float*)d_in[0];
    const float* W = (const float*)d_in[1];
    const float* b = (const float*)d_in[2];
    const int* kp = (n_in > 3) ? (const int*)d_in[3] : nullptr;
    float* out = (float*)d_out;

    cudaFuncSetAttribute(router_gemm_kernel,
                         cudaFuncAttributeMaxDynamicSharedMemorySize, SMEM1);

    const int N = in_sizes[0] / D;                        // 8192
    router_gemm_kernel<<<N / BM, NT1, SMEM1>>>(z, W, b);
    router_refine_kernel<<<N / 8, 256>>>(z, W, b, kp, out);
    (void)out_size;
}

// round 13
// speedup vs baseline: 1.6221x; 1.6221x over previous
#include <cuda_runtime.h>
#include <cuda_fp16.h>
#include <cstdint>

// Router: alpha = softmax(topk_mask(z @ W^T + b))
// z:[8192,4096]f32  W:[64,4096]f32  b:[64]f32  k=2
// K1: split-K(4) GEMM, fp16 2-tier split (z=z1+z2, 64W=w1+w2),
//     mma.sync m16n8k16, 3-stage ring, prefetch-2.  Scratch (8MB) stays in L2.
// K2: reduce 4 partials, *1/64, +bias, top-k mask, softmax.

namespace {
typedef uint32_t u32;
constexpr int D = 4096;
constexpr int KSPLIT = 4;
constexpr int KH = D / KSPLIT;       // 1024
constexpr int BM = 64;
constexpr int BK = 32;
constexpr int NSTG = KH / BK;        // 32
constexpr int NT1 = 256;
constexpr int Kc = 64;
constexpr int NROWS = 8192;

constexpr int ROWB = 80;             // 32 halfs + 8 pad; ldsm conflict-free
constexpr int A1_OFF = 0;            // 64*80 = 5120B per tier
constexpr int A2_OFF = 5120;
constexpr int B1_OFF = 10240;
constexpr int B2_OFF = 15360;
constexpr int STG_B = 20480;
constexpr int SMEM1 = 3 * STG_B;     // 61440 dynamic

__device__ float g_part[KSPLIT * NROWS * Kc];  // 8MB scratch (L2-resident)

__device__ __forceinline__ void mma16(float* d, const u32* a, u32 b0, u32 b1) {
    asm volatile(
        "mma.sync.aligned.m16n8k16.row.col.f32.f16.f16.f32 "
        "{%0,%1,%2,%3}, {%4,%5,%6,%7}, {%8,%9}, {%0,%1,%2,%3};"
        : "+f"(d[0]), "+f"(d[1]), "+f"(d[2]), "+f"(d[3])
        : "r"(a[0]), "r"(a[1]), "r"(a[2]), "r"(a[3]), "r"(b0), "r"(b1));
}
__device__ __forceinline__ void ldsm4(u32* r, u32 addr) {
    asm volatile(
        "ldmatrix.sync.aligned.m8n8.x4.shared.b16 {%0,%1,%2,%3}, [%4];"
        : "=r"(r[0]), "=r"(r[1]), "=r"(r[2]), "=r"(r[3]) : "r"(addr));
}
__device__ __forceinline__ u32 smem_u32(const void* p) {
    u32 a;
    asm("{ .reg .u64 t; cvta.to.shared.u64 t, %1; cvt.u32.u64 %0, t; }"
        : "=r"(a) : "l"(p));
    return a;
}
// 2-tier split: h1 = rn(v), h2 = rn(v - h1); v = h1 + h2 + O(2^-22 |v|)
__device__ __forceinline__ void split_pack(float4 v, uint2& t1, uint2& t2) {
    __half hx = __float2half_rn(v.x), hy = __float2half_rn(v.y),
           hz = __float2half_rn(v.z), hw = __float2half_rn(v.w);
    float rx = v.x - __half2float(hx), ry = v.y - __half2float(hy),
          rz = v.z - __half2float(hz), rw = v.w - __half2float(hw);
    __half lx = __float2half_rn(rx), ly = __float2half_rn(ry),
           lz = __float2half_rn(rz), lw = __float2half_rn(rw);
    t1.x = (u32)__half_as_ushort(hx) | ((u32)__half_as_ushort(hy) << 16);
    t1.y = (u32)__half_as_ushort(hz) | ((u32)__half_as_ushort(hw) << 16);
    t2.x = (u32)__half_as_ushort(lx) | ((u32)__half_as_ushort(ly) << 16);
    t2.y = (u32)__half_as_ushort(lz) | ((u32)__half_as_ushort(lw) << 16);
}
} // namespace

extern __shared__ __align__(16) char smem1[];

__global__ __launch_bounds__(NT1, 3) void router_gemm_kernel(
    const float* __restrict__ z, const float* __restrict__ W)
{
    const int tid = threadIdx.x;
    const int wid = tid >> 5;
    const int lane = tid & 31;
    const int rb = blockIdx.x >> 2;       // row block (0..127)
    const int ks = blockIdx.x & 3;        // k quarter
    const int row0 = rb * BM;
    const int kbase = ks * KH;

    // ---- producer mapping: rows ar, ar+32 of both A and B ----
    const int ar = tid >> 3;              // 0..31
    const int kg = tid & 7;
    const float* zg0 = z + (size_t)(row0 + ar) * D + kbase + kg * 4;
    const float* zg1 = zg0 + (size_t)32 * D;
    const float* wg0 = W + (size_t)ar * D + kbase + kg * 4;
    const float* wg1 = wg0 + (size_t)32 * D;
    const int sts0 = ar * ROWB + kg * 8;
    const int sts1 = (ar + 32) * ROWB + kg * 8;

    // ---- consumer: warp (mw 0..1, nw 0..3), tile m32 x n16 ----
    const int mw = wid & 1;
    const int nw = wid >> 1;
    const u32 sb = smem_u32(smem1);
    const u32 aB = sb + (u32)((mw * 32 + (lane & 15)) * ROWB + (lane >> 4) * 16);
    const u32 bB = sb + (u32)(B1_OFF + (nw * 16 + (lane & 7) + ((lane >> 4) << 3)) * ROWB
                              + (((lane >> 3) & 1) * 16));

    float acc[2][2][4];
#pragma unroll
    for (int i = 0; i < 2; ++i)
#pragma unroll
        for (int j = 0; j < 2; ++j)
#pragma unroll
            for (int q = 0; q < 4; ++q) acc[i][j][q] = 0.f;

    float4 va0, va1, vb0, vb1;

#define LDG_STAGE(t)                                        \
    do {                                                    \
        va0 = *(const float4*)(zg0 + (t) * BK);             \
        va1 = *(const float4*)(zg1 + (t) * BK);             \
        vb0 = *(const float4*)(wg0 + (t) * BK);             \
        vb1 = *(const float4*)(wg1 + (t) * BK);             \
    } while (0)

#define STS_STAGE(buf)                                      \
    do {                                                    \
        char* s_ = smem1 + (buf) * STG_B;                   \
        uint2 t1, t2;                                       \
        split_pack(va0, t1, t2);                            \
        *(uint2*)(s_ + A1_OFF + sts0) = t1;                 \
        *(uint2*)(s_ + A2_OFF + sts0) = t2;                 \
        split_pack(va1, t1, t2);                            \
        *(uint2*)(s_ + A1_OFF + sts1) = t1;                 \
        *(uint2*)(s_ + A2_OFF + sts1) = t2;                 \
        float4 w0 = make_float4(vb0.x * 64.f, vb0.y * 64.f, \
                                vb0.z * 64.f, vb0.w * 64.f);\
        split_pack(w0, t1, t2);                             \
        *(uint2*)(s_ + B1_OFF + sts0) = t1;                 \
        *(uint2*)(s_ + B2_OFF + sts0) = t2;                 \
        float4 w1 = make_float4(vb1.x * 64.f, vb1.y * 64.f, \
                                vb1.z * 64.f, vb1.w * 64.f);\
        split_pack(w1, t1, t2);                             \
        *(uint2*)(s_ + B1_OFF + sts1) = t1;                 \
        *(uint2*)(s_ + B2_OFF + sts1) = t2;                 \
    } while (0)

    LDG_STAGE(0);
    STS_STAGE(0);
    LDG_STAGE(1);
    STS_STAGE(1);
    LDG_STAGE(2);
    __syncthreads();

#pragma unroll 4
    for (int t = 0; t < NSTG; ++t) {
        const u32 so = (u32)((t % 3) * STG_B);
#pragma unroll
        for (int kc = 0; kc < 2; ++kc) {
            const u32 ko = kc * 32;  // 16 halfs
            u32 b1r[4], b2r[4];
            ldsm4(b1r, bB + so + ko);
            ldsm4(b2r, bB + so + ko + (B2_OFF - B1_OFF));
#pragma unroll
            for (int ms = 0; ms < 2; ++ms) {
                const u32 mo = (u32)(ms * 16 * ROWB);
                u32 a1r[4], a2r[4];
                ldsm4(a1r, aB + so + mo + ko);
                ldsm4(a2r, aB + so + mo + ko + A2_OFF);
                mma16(acc[ms][0], a1r, b1r[0], b1r[1]);
                mma16(acc[ms][0], a1r, b2r[0], b2r[1]);
                mma16(acc[ms][0], a2r, b1r[0], b1r[1]);
                mma16(acc[ms][1], a1r, b1r[2], b1r[3]);
                mma16(acc[ms][1], a1r, b2r[2], b2r[3]);
                mma16(acc[ms][1], a2r, b1r[2], b1r[3]);
            }
        }
        if (t + 2 < NSTG) STS_STAGE((t + 2) % 3);
        if (t + 3 < NSTG) LDG_STAGE(t + 3);
        __syncthreads();
    }

    // ---- write partial logits (scaled by 64) ----
    float* gp = g_part + (size_t)ks * NROWS * Kc;
    const int rr = lane >> 2;
    const int cc = (lane & 3) * 2;
#pragma unroll
    for (int ms = 0; ms < 2; ++ms) {
        const int row = row0 + mw * 32 + ms * 16 + rr;
#pragma unroll
        for (int nb = 0; nb < 2; ++nb) {
            const int col = nw * 16 + nb * 8 + cc;
            *(float2*)(gp + (size_t)row * Kc + col) =
                make_float2(acc[ms][nb][0], acc[ms][nb][1]);
            *(float2*)(gp + (size_t)(row + 8) * Kc + col) =
                make_float2(acc[ms][nb][2], acc[ms][nb][3]);
        }
    }
#undef LDG_STAGE
#undef STS_STAGE
}

// ---- K2: reduce partials + bias + top-k + softmax (warp per row) ----
__global__ __launch_bounds__(256, 8) void router_topk_kernel(
    const float* __restrict__ b, const int* __restrict__ kptr,
    float* __restrict__ out)
{
    const int wid = threadIdx.x >> 5;
    const int lane = threadIdx.x & 31;
    const int row = blockIdx.x * 8 + wid;
    const int c0 = lane * 2;

    float v0 = 0.f, v1 = 0.f;
#pragma unroll
    for (int ks = 0; ks < KSPLIT; ++ks) {
        const float2 p = *(const float2*)(
            g_part + (size_t)ks * NROWS * Kc + (size_t)row * Kc + c0);
        v0 += p.x;
        v1 += p.y;
    }
    v0 = v0 * 0.015625f + b[c0];
    v1 = v1 * 0.015625f + b[c0 + 1];

    int kk = kptr ? *kptr : 2;
    if (kk < 1) kk = 1;
    if (kk > Kc) kk = Kc;

    if (kk == 2) {
        // one-pass top-2 (val desc, idx asc — jax.lax.top_k tie-break)
        float hv, lv;
        int hi_, li_;
        if (v1 > v0) { hv = v1; hi_ = c0 + 1; lv = v0; li_ = c0; }
        else         { hv = v0; hi_ = c0;     lv = v1; li_ = c0 + 1; }
#pragma unroll
        for (int off = 16; off; off >>= 1) {
            const float ohv = __shfl_xor_sync(0xffffffffu, hv, off);
            const float olv = __shfl_xor_sync(0xffffffffu, lv, off);
            const int ohi = __shfl_xor_sync(0xffffffffu, hi_, off);
            const int oli = __shfl_xor_sync(0xffffffffu, li_, off);
            const bool w1_ = (hv > ohv) || (hv == ohv && hi_ < ohi);
            const float whv = w1_ ? hv : ohv;
            const int   whi = w1_ ? hi_ : ohi;
            const float lsv = w1_ ? ohv : hv;
            const int   lsi = w1_ ? ohi : hi_;
            const float wlv = w1_ ? lv : olv;
            const int   wli = w1_ ? li_ : oli;
            const bool sw = (lsv > wlv) || (lsv == wlv && lsi < wli);
            hv = whv; hi_ = whi;
            lv = sw ? lsv : wlv;
            li_ = sw ? lsi : wli;
        }
        const float elo = expf(lv - hv);
        const float inv = 1.0f / (1.0f + elo);
        const float eli = elo * inv;
        const float o0 = (c0 == hi_) ? inv : ((c0 == li_) ? eli : 0.f);
        const float o1 = (c0 + 1 == hi_) ? inv : ((c0 + 1 == li_) ? eli : 0.f);
        *(float2*)(out + (size_t)row * Kc + c0) = make_float2(o0, o1);
        return;
    }

    // generic k path
    unsigned sel = 0;
    float m = 0.f;
    for (int p = 0; p < kk; ++p) {
        float bv = (sel & 1) ? -3.4e38f : v0;
        int bi = c0;
        const float c1v = (sel & 2) ? -3.4e38f : v1;
        if (c1v > bv) { bv = c1v; bi = c0 + 1; }
#pragma unroll
        for (int off = 16; off; off >>= 1) {
            const float ov = __shfl_xor_sync(0xffffffffu, bv, off);
            const int oi = __shfl_xor_sync(0xffffffffu, bi, off);
            if (ov > bv || (ov == bv && oi < bi)) { bv = ov; bi = oi; }
        }
        if (p == 0) m = bv;
        if ((bi >> 1) == lane) sel |= 1u << (bi & 1);
    }
    const float e0 = (sel & 1) ? expf(v0 - m) : 0.f;
    const float e1 = (sel & 2) ? expf(v1 - m) : 0.f;
    float s = e0 + e1;
#pragma unroll
    for (int off = 16; off; off >>= 1) s += __shfl_xor_sync(0xffffffffu, s, off);
    const float inv = 1.0f / s;
    *(float2*)(out + (size_t)row * Kc + c0) = make_float2(e0 * inv, e1 * inv);
}

extern "C" void kernel_launch(void* const* d_in, const int* in_sizes, int n_in,
                              void* d_out, int out_size) {
    const float* z = (const float*)d_in[0];
    const float* W = (const float*)d_in[1];
    const float* b = (const float*)d_in[2];
    const int* kp = (n_in > 3) ? (const int*)d_in[3] : nullptr;
    float* out = (float*)d_out;

    cudaFuncSetAttribute(router_gemm_kernel,
                         cudaFuncAttributeMaxDynamicSharedMemorySize, SMEM1);

    const int N = in_sizes[0] / D;                      // 8192
    router_gemm_kernel<<<(N / BM) * KSPLIT, NT1, SMEM1>>>(z, W);
    router_topk_kernel<<<N / 8, 256>>>(b, kp, out);
    (void)out_size;
}

// round 14
// speedup vs baseline: 1.9249x; 1.1866x over previous
#include <cuda_runtime.h>
#include <cuda_fp16.h>
#include <cstdint>

// Router: alpha = softmax(topk_mask(z @ W^T + b))
// z:[8192,4096]f32  W:[64,4096]f32  b:[64]f32  k=2
// K1: PERSISTENT split-K(8) GEMM, dynamic (rb,ks) items, fp16 2-tier split
//     (z=z1+z2, 64W=w1+w2), mma.sync m16n8k16, 3-stage ring, prefetch-2.
// K2: reduce 8 partials, *1/64, +bias, top-k mask, softmax.

namespace {
typedef uint32_t u32;
constexpr int D = 4096;
constexpr int KSPLIT = 8;
constexpr int KH = D / KSPLIT;       // 512
constexpr int BM = 64;
constexpr int BK = 32;
constexpr int NSTG = KH / BK;        // 16
constexpr int NT1 = 256;
constexpr int Kc = 64;
constexpr int NROWS = 8192;
constexpr int NITEMS = (NROWS / BM) * KSPLIT;  // 1024
constexpr int GRID1 = 456;           // 3 per SM

constexpr int ROWB = 80;             // 32 halfs + 8 pad; ldsm conflict-free
constexpr int A1_OFF = 0;            // 64*80 = 5120B per tier
constexpr int A2_OFF = 5120;
constexpr int B1_OFF = 10240;
constexpr int B2_OFF = 15360;
constexpr int STG_B = 20480;
constexpr int SMEM1 = 3 * STG_B;     // 61440 dynamic

__device__ float g_part[KSPLIT * NROWS * Kc];  // 16MB scratch
__device__ int g_item;

__device__ __forceinline__ void mma16(float* d, const u32* a, u32 b0, u32 b1) {
    asm volatile(
        "mma.sync.aligned.m16n8k16.row.col.f32.f16.f16.f32 "
        "{%0,%1,%2,%3}, {%4,%5,%6,%7}, {%8,%9}, {%0,%1,%2,%3};"
        : "+f"(d[0]), "+f"(d[1]), "+f"(d[2]), "+f"(d[3])
        : "r"(a[0]), "r"(a[1]), "r"(a[2]), "r"(a[3]), "r"(b0), "r"(b1));
}
__device__ __forceinline__ void ldsm4(u32* r, u32 addr) {
    asm volatile(
        "ldmatrix.sync.aligned.m8n8.x4.shared.b16 {%0,%1,%2,%3}, [%4];"
        : "=r"(r[0]), "=r"(r[1]), "=r"(r[2]), "=r"(r[3]) : "r"(addr));
}
__device__ __forceinline__ u32 smem_u32(const void* p) {
    u32 a;
    asm("{ .reg .u64 t; cvta.to.shared.u64 t, %1; cvt.u32.u64 %0, t; }"
        : "=r"(a) : "l"(p));
    return a;
}
// 2-tier split: h1 = rn(v), h2 = rn(v - h1); v = h1 + h2 + O(2^-22 |v|)
__device__ __forceinline__ void split_pack(float4 v, uint2& t1, uint2& t2) {
    __half hx = __float2half_rn(v.x), hy = __float2half_rn(v.y),
           hz = __float2half_rn(v.z), hw = __float2half_rn(v.w);
    float rx = v.x - __half2float(hx), ry = v.y - __half2float(hy),
          rz = v.z - __half2float(hz), rw = v.w - __half2float(hw);
    __half lx = __float2half_rn(rx), ly = __float2half_rn(ry),
           lz = __float2half_rn(rz), lw = __float2half_rn(rw);
    t1.x = (u32)__half_as_ushort(hx) | ((u32)__half_as_ushort(hy) << 16);
    t1.y = (u32)__half_as_ushort(hz) | ((u32)__half_as_ushort(hw) << 16);
    t2.x = (u32)__half_as_ushort(lx) | ((u32)__half_as_ushort(ly) << 16);
    t2.y = (u32)__half_as_ushort(lz) | ((u32)__half_as_ushort(lw) << 16);
}
} // namespace

__global__ void router_zero() { g_item = 0; }

extern __shared__ __align__(16) char smem1[];

__global__ __launch_bounds__(NT1, 3) void router_gemm_kernel(
    const float* __restrict__ z, const float* __restrict__ W)
{
    __shared__ int s_item;

    const int tid = threadIdx.x;
    const int wid = tid >> 5;
    const int lane = tid & 31;

    // producer mapping (item-independent parts)
    const int ar = tid >> 3;              // 0..31
    const int kg = tid & 7;
    const int sts0 = ar * ROWB + kg * 8;
    const int sts1 = (ar + 32) * ROWB + kg * 8;

    // consumer mapping
    const int mw = wid & 1;
    const int nw = wid >> 1;
    const u32 sb = smem_u32(smem1);
    const u32 aB = sb + (u32)((mw * 32 + (lane & 15)) * ROWB + (lane >> 4) * 16);
    const u32 bB = sb + (u32)(B1_OFF + (nw * 16 + (lane & 7) + ((lane >> 4) << 3)) * ROWB
                              + (((lane >> 3) & 1) * 16));

    for (;;) {
        if (tid == 0) s_item = atomicAdd(&g_item, 1);
        __syncthreads();
        const int item = s_item;
        __syncthreads();
        if (item >= NITEMS) break;

        const int rb = item >> 3;
        const int ks = item & 7;
        const int row0 = rb * BM;
        const int kbase = ks * KH;

        const float* zg0 = z + (size_t)(row0 + ar) * D + kbase + kg * 4;
        const float* zg1 = zg0 + (size_t)32 * D;
        const float* wg0 = W + (size_t)ar * D + kbase + kg * 4;
        const float* wg1 = wg0 + (size_t)32 * D;

        float acc[2][2][4];
#pragma unroll
        for (int i = 0; i < 2; ++i)
#pragma unroll
            for (int j = 0; j < 2; ++j)
#pragma unroll
                for (int q = 0; q < 4; ++q) acc[i][j][q] = 0.f;

        float4 va0, va1, vb0, vb1;

#define LDG_STAGE(t)                                        \
    do {                                                    \
        va0 = *(const float4*)(zg0 + (t) * BK);             \
        va1 = *(const float4*)(zg1 + (t) * BK);             \
        vb0 = *(const float4*)(wg0 + (t) * BK);             \
        vb1 = *(const float4*)(wg1 + (t) * BK);             \
    } while (0)

#define STS_STAGE(buf)                                      \
    do {                                                    \
        char* s_ = smem1 + (buf) * STG_B;                   \
        uint2 t1, t2;                                       \
        split_pack(va0, t1, t2);                            \
        *(uint2*)(s_ + A1_OFF + sts0) = t1;                 \
        *(uint2*)(s_ + A2_OFF + sts0) = t2;                 \
        split_pack(va1, t1, t2);                            \
        *(uint2*)(s_ + A1_OFF + sts1) = t1;                 \
        *(uint2*)(s_ + A2_OFF + sts1) = t2;                 \
        float4 w0 = make_float4(vb0.x * 64.f, vb0.y * 64.f, \
                                vb0.z * 64.f, vb0.w * 64.f);\
        split_pack(w0, t1, t2);                             \
        *(uint2*)(s_ + B1_OFF + sts0) = t1;                 \
        *(uint2*)(s_ + B2_OFF + sts0) = t2;                 \
        float4 w1 = make_float4(vb1.x * 64.f, vb1.y * 64.f, \
                                vb1.z * 64.f, vb1.w * 64.f);\
        split_pack(w1, t1, t2);                             \
        *(uint2*)(s_ + B1_OFF + sts1) = t1;                 \
        *(uint2*)(s_ + B2_OFF + sts1) = t2;                 \
    } while (0)

        LDG_STAGE(0);
        STS_STAGE(0);
        LDG_STAGE(1);
        STS_STAGE(1);
        LDG_STAGE(2);
        __syncthreads();

#pragma unroll
        for (int t = 0; t < NSTG; ++t) {
            const u32 so = (u32)((t % 3) * STG_B);
#pragma unroll
            for (int kc = 0; kc < 2; ++kc) {
                const u32 ko = kc * 32;  // 16 halfs
                u32 b1r[4], b2r[4];
                ldsm4(b1r, bB + so + ko);
                ldsm4(b2r, bB + so + ko + (B2_OFF - B1_OFF));
#pragma unroll
                for (int ms = 0; ms < 2; ++ms) {
                    const u32 mo = (u32)(ms * 16 * ROWB);
                    u32 a1r[4], a2r[4];
                    ldsm4(a1r, aB + so + mo + ko);
                    ldsm4(a2r, aB + so + mo + ko + A2_OFF);
                    mma16(acc[ms][0], a1r, b1r[0], b1r[1]);
                    mma16(acc[ms][0], a1r, b2r[0], b2r[1]);
                    mma16(acc[ms][0], a2r, b1r[0], b1r[1]);
                    mma16(acc[ms][1], a1r, b1r[2], b1r[3]);
                    mma16(acc[ms][1], a1r, b2r[2], b2r[3]);
                    mma16(acc[ms][1], a2r, b1r[2], b1r[3]);
                }
            }
            if (t + 2 < NSTG) STS_STAGE((t + 2) % 3);
            if (t + 3 < NSTG) LDG_STAGE(t + 3);
            __syncthreads();
        }

        // ---- write partial logits (scaled by 64) ----
        float* gp = g_part + (size_t)ks * NROWS * Kc;
        const int rr = lane >> 2;
        const int cc = (lane & 3) * 2;
#pragma unroll
        for (int ms = 0; ms < 2; ++ms) {
            const int row = row0 + mw * 32 + ms * 16 + rr;
#pragma unroll
            for (int nb = 0; nb < 2; ++nb) {
                const int col = nw * 16 + nb * 8 + cc;
                *(float2*)(gp + (size_t)row * Kc + col) =
                    make_float2(acc[ms][nb][0], acc[ms][nb][1]);
                *(float2*)(gp + (size_t)(row + 8) * Kc + col) =
                    make_float2(acc[ms][nb][2], acc[ms][nb][3]);
            }
        }
        __syncthreads();  // all STS consumed before next item's preamble reuses ring
#undef LDG_STAGE
#undef STS_STAGE
    }
}

// ---- K2: reduce partials + bias + top-k + softmax (warp per row) ----
__global__ __launch_bounds__(256, 8) void router_topk_kernel(
    const float* __restrict__ b, const int* __restrict__ kptr,
    float* __restrict__ out)
{
    const int wid = threadIdx.x >> 5;
    const int lane = threadIdx.x & 31;
    const int row = blockIdx.x * 8 + wid;
    const int c0 = lane * 2;

    float v0 = 0.f, v1 = 0.f;
#pragma unroll
    for (int ks = 0; ks < KSPLIT; ++ks) {
        const float2 p = *(const float2*)(
            g_part + (size_t)ks * NROWS * Kc + (size_t)row * Kc + c0);
        v0 += p.x;
        v1 += p.y;
    }
    v0 = v0 * 0.015625f + b[c0];
    v1 = v1 * 0.015625f + b[c0 + 1];

    int kk = kptr ? *kptr : 2;
    if (kk < 1) kk = 1;
    if (kk > Kc) kk = Kc;

    if (kk == 2) {
        // one-pass top-2 (val desc, idx asc — jax.lax.top_k tie-break)
        float hv, lv;
        int hi_, li_;
        if (v1 > v0) { hv = v1; hi_ = c0 + 1; lv = v0; li_ = c0; }
        else         { hv = v0; hi_ = c0;     lv = v1; li_ = c0 + 1; }
#pragma unroll
        for (int off = 16; off; off >>= 1) {
            const float ohv = __shfl_xor_sync(0xffffffffu, hv, off);
            const float olv = __shfl_xor_sync(0xffffffffu, lv, off);
            const int ohi = __shfl_xor_sync(0xffffffffu, hi_, off);
            const int oli = __shfl_xor_sync(0xffffffffu, li_, off);
            const bool w1_ = (hv > ohv) || (hv == ohv && hi_ < ohi);
            const float whv = w1_ ? hv : ohv;
            const int   whi = w1_ ? hi_ : ohi;
            const float lsv = w1_ ? ohv : hv;
            const int   lsi = w1_ ? ohi : hi_;
            const float wlv = w1_ ? lv : olv;
            const int   wli = w1_ ? li_ : oli;
            const bool sw = (lsv > wlv) || (lsv == wlv && lsi < wli);
            hv = whv; hi_ = whi;
            lv = sw ? lsv : wlv;
            li_ = sw ? lsi : wli;
        }
        const float elo = expf(lv - hv);
        const float inv = 1.0f / (1.0f + elo);
        const float eli = elo * inv;
        const float o0 = (c0 == hi_) ? inv : ((c0 == li_) ? eli : 0.f);
        const float o1 = (c0 + 1 == hi_) ? inv : ((c0 + 1 == li_) ? eli : 0.f);
        *(float2*)(out + (size_t)row * Kc + c0) = make_float2(o0, o1);
        return;
    }

    // generic k path
    unsigned sel = 0;
    float m = 0.f;
    for (int p = 0; p < kk; ++p) {
        float bv = (sel & 1) ? -3.4e38f : v0;
        int bi = c0;
        const float c1v = (sel & 2) ? -3.4e38f : v1;
        if (c1v > bv) { bv = c1v; bi = c0 + 1; }
#pragma unroll
        for (int off = 16; off; off >>= 1) {
            const float ov = __shfl_xor_sync(0xffffffffu, bv, off);
            const int oi = __shfl_xor_sync(0xffffffffu, bi, off);
            if (ov > bv || (ov == bv && oi < bi)) { bv = ov; bi = oi; }
        }
        if (p == 0) m = bv;
        if ((bi >> 1) == lane) sel |= 1u << (bi & 1);
    }
    const float e0 = (sel & 1) ? expf(v0 - m) : 0.f;
    const float e1 = (sel & 2) ? expf(v1 - m) : 0.f;
    float s = e0 + e1;
#pragma unroll
    for (int off = 16; off; off >>= 1) s += __shfl_xor_sync(0xffffffffu, s, off);
    const float inv = 1.0f / s;
    *(float2*)(out + (size_t)row * Kc + c0) = make_float2(e0 * inv, e1 * inv);
}

extern "C" void kernel_launch(void* const* d_in, const int* in_sizes, int n_in,
                              void* d_out, int out_size) {
    const float* z = (const float*)d_in[0];
    const float* W = (const float*)d_in[1];
    const float* b = (const float*)d_in[2];
    const int* kp = (n_in > 3) ? (const int*)d_in[3] : nullptr;
    float* out = (float*)d_out;

    cudaFuncSetAttribute(router_gemm_kernel,
                         cudaFuncAttributeMaxDynamicSharedMemorySize, SMEM1);

    const int N = in_sizes[0] / D;                      // 8192
    router_zero<<<1, 1>>>();
    router_gemm_kernel<<<GRID1, NT1, SMEM1>>>(z, W);
    router_topk_kernel<<<N / 8, 256>>>(b, kp, out);
    (void)out_size;
}

// round 15
// speedup vs baseline: 1.9523x; 1.0143x over previous
#include <cuda_runtime.h>
#include <cuda_fp16.h>
#include <cstdint>

// Router: alpha = softmax(topk_mask(z @ W^T + b))
// z:[8192,4096]f32  W:[64,4096]f32  b:[64]f32  k=2
// K1: PERSISTENT split-K(8) GEMM, dynamic (rb,ks) items, fp16 2-tier split
//     (z=z1+z2, 64W=w1+w2), mma.sync m16n8k16, 3-stage ring, prefetch-2.
// K2: reduce 8 partials, *1/64, +bias, top-k mask, softmax; resets the
//     work counter for the next launch (no separate zero kernel).

namespace {
typedef uint32_t u32;
constexpr int D = 4096;
constexpr int KSPLIT = 8;
constexpr int KH = D / KSPLIT;       // 512
constexpr int BM = 64;
constexpr int BK = 32;
constexpr int NSTG = KH / BK;        // 16
constexpr int NT1 = 256;
constexpr int Kc = 64;
constexpr int NROWS = 8192;
constexpr int NITEMS = (NROWS / BM) * KSPLIT;  // 1024
constexpr int GRID1 = 456;           // 3 per SM

constexpr int ROWB = 80;             // 32 halfs + 8 pad; ldsm conflict-free
constexpr int A1_OFF = 0;            // 64*80 = 5120B per tier
constexpr int A2_OFF = 5120;
constexpr int B1_OFF = 10240;
constexpr int B2_OFF = 15360;
constexpr int STG_B = 20480;
constexpr int SMEM1 = 3 * STG_B;     // 61440 dynamic

__device__ float g_part[KSPLIT * NROWS * Kc];  // 16MB scratch
__device__ int g_item;                          // static-init 0; topk resets

__device__ __forceinline__ void mma16(float* d, const u32* a, u32 b0, u32 b1) {
    asm volatile(
        "mma.sync.aligned.m16n8k16.row.col.f32.f16.f16.f32 "
        "{%0,%1,%2,%3}, {%4,%5,%6,%7}, {%8,%9}, {%0,%1,%2,%3};"
        : "+f"(d[0]), "+f"(d[1]), "+f"(d[2]), "+f"(d[3])
        : "r"(a[0]), "r"(a[1]), "r"(a[2]), "r"(a[3]), "r"(b0), "r"(b1));
}
__device__ __forceinline__ void ldsm4(u32* r, u32 addr) {
    asm volatile(
        "ldmatrix.sync.aligned.m8n8.x4.shared.b16 {%0,%1,%2,%3}, [%4];"
        : "=r"(r[0]), "=r"(r[1]), "=r"(r[2]), "=r"(r[3]) : "r"(addr));
}
__device__ __forceinline__ u32 smem_u32(const void* p) {
    u32 a;
    asm("{ .reg .u64 t; cvta.to.shared.u64 t, %1; cvt.u32.u64 %0, t; }"
        : "=r"(a) : "l"(p));
    return a;
}
// 2-tier split: h1 = rn(v), h2 = rn(v - h1); v = h1 + h2 + O(2^-22 |v|)
__device__ __forceinline__ void split_pack(float4 v, uint2& t1, uint2& t2) {
    __half hx = __float2half_rn(v.x), hy = __float2half_rn(v.y),
           hz = __float2half_rn(v.z), hw = __float2half_rn(v.w);
    float rx = v.x - __half2float(hx), ry = v.y - __half2float(hy),
          rz = v.z - __half2float(hz), rw = v.w - __half2float(hw);
    __half lx = __float2half_rn(rx), ly = __float2half_rn(ry),
           lz = __float2half_rn(rz), lw = __float2half_rn(rw);
    t1.x = (u32)__half_as_ushort(hx) | ((u32)__half_as_ushort(hy) << 16);
    t1.y = (u32)__half_as_ushort(hz) | ((u32)__half_as_ushort(hw) << 16);
    t2.x = (u32)__half_as_ushort(lx) | ((u32)__half_as_ushort(ly) << 16);
    t2.y = (u32)__half_as_ushort(lz) | ((u32)__half_as_ushort(lw) << 16);
}
} // namespace

extern __shared__ __align__(16) char smem1[];

__global__ __launch_bounds__(NT1, 3) void router_gemm_kernel(
    const float* __restrict__ z, const float* __restrict__ W)
{
    __shared__ int s_item;

    const int tid = threadIdx.x;
    const int wid = tid >> 5;
    const int lane = tid & 31;

    // producer mapping (item-independent parts)
    const int ar = tid >> 3;              // 0..31
    const int kg = tid & 7;
    const int sts0 = ar * ROWB + kg * 8;
    const int sts1 = (ar + 32) * ROWB + kg * 8;

    // consumer mapping
    const int mw = wid & 1;
    const int nw = wid >> 1;
    const u32 sb = smem_u32(smem1);
    const u32 aB = sb + (u32)((mw * 32 + (lane & 15)) * ROWB + (lane >> 4) * 16);
    const u32 bB = sb + (u32)(B1_OFF + (nw * 16 + (lane & 7) + ((lane >> 4) << 3)) * ROWB
                              + (((lane >> 3) & 1) * 16));

    for (;;) {
        if (tid == 0) s_item = atomicAdd(&g_item, 1);
        __syncthreads();
        const int item = s_item;  // next write of s_item is behind trailing sync
        if (item >= NITEMS) break;

        const int rb = item >> 3;
        const int ks = item & 7;
        const int row0 = rb * BM;
        const int kbase = ks * KH;

        const float* zg0 = z + (size_t)(row0 + ar) * D + kbase + kg * 4;
        const float* zg1 = zg0 + (size_t)32 * D;
        const float* wg0 = W + (size_t)ar * D + kbase + kg * 4;
        const float* wg1 = wg0 + (size_t)32 * D;

        float acc[2][2][4];
#pragma unroll
        for (int i = 0; i < 2; ++i)
#pragma unroll
            for (int j = 0; j < 2; ++j)
#pragma unroll
                for (int q = 0; q < 4; ++q) acc[i][j][q] = 0.f;

        float4 va0, va1, vb0, vb1;

#define LDG_STAGE(t)                                        \
    do {                                                    \
        va0 = *(const float4*)(zg0 + (t) * BK);             \
        va1 = *(const float4*)(zg1 + (t) * BK);             \
        vb0 = *(const float4*)(wg0 + (t) * BK);             \
        vb1 = *(const float4*)(wg1 + (t) * BK);             \
    } while (0)

#define STS_STAGE(buf)                                      \
    do {                                                    \
        char* s_ = smem1 + (buf) * STG_B;                   \
        uint2 t1, t2;                                       \
        split_pack(va0, t1, t2);                            \
        *(uint2*)(s_ + A1_OFF + sts0) = t1;                 \
        *(uint2*)(s_ + A2_OFF + sts0) = t2;                 \
        split_pack(va1, t1, t2);                            \
        *(uint2*)(s_ + A1_OFF + sts1) = t1;                 \
        *(uint2*)(s_ + A2_OFF + sts1) = t2;                 \
        float4 w0 = make_float4(vb0.x * 64.f, vb0.y * 64.f, \
                                vb0.z * 64.f, vb0.w * 64.f);\
        split_pack(w0, t1, t2);                             \
        *(uint2*)(s_ + B1_OFF + sts0) = t1;                 \
        *(uint2*)(s_ + B2_OFF + sts0) = t2;                 \
        float4 w1 = make_float4(vb1.x * 64.f, vb1.y * 64.f, \
                                vb1.z * 64.f, vb1.w * 64.f);\
        split_pack(w1, t1, t2);                             \
        *(uint2*)(s_ + B1_OFF + sts1) = t1;                 \
        *(uint2*)(s_ + B2_OFF + sts1) = t2;                 \
    } while (0)

        LDG_STAGE(0);
        STS_STAGE(0);
        LDG_STAGE(1);
        STS_STAGE(1);
        LDG_STAGE(2);
        __syncthreads();

#pragma unroll
        for (int t = 0; t < NSTG; ++t) {
            const u32 so = (u32)((t % 3) * STG_B);
#pragma unroll
            for (int kc = 0; kc < 2; ++kc) {
                const u32 ko = kc * 32;  // 16 halfs
                u32 b1r[4], b2r[4];
                ldsm4(b1r, bB + so + ko);
                ldsm4(b2r, bB + so + ko + (B2_OFF - B1_OFF));
#pragma unroll
                for (int ms = 0; ms < 2; ++ms) {
                    const u32 mo = (u32)(ms * 16 * ROWB);
                    u32 a1r[4], a2r[4];
                    ldsm4(a1r, aB + so + mo + ko);
                    ldsm4(a2r, aB + so + mo + ko + A2_OFF);
                    mma16(acc[ms][0], a1r, b1r[0], b1r[1]);
                    mma16(acc[ms][0], a1r, b2r[0], b2r[1]);
                    mma16(acc[ms][0], a2r, b1r[0], b1r[1]);
                    mma16(acc[ms][1], a1r, b1r[2], b1r[3]);
                    mma16(acc[ms][1], a1r, b2r[2], b2r[3]);
                    mma16(acc[ms][1], a2r, b1r[2], b1r[3]);
                }
            }
            if (t + 2 < NSTG) STS_STAGE((t + 2) % 3);
            if (t + 3 < NSTG) LDG_STAGE(t + 3);
            __syncthreads();
        }

        // ---- write partial logits (scaled by 64) ----
        float* gp = g_part + (size_t)ks * NROWS * Kc;
        const int rr = lane >> 2;
        const int cc = (lane & 3) * 2;
#pragma unroll
        for (int ms = 0; ms < 2; ++ms) {
            const int row = row0 + mw * 32 + ms * 16 + rr;
#pragma unroll
            for (int nb = 0; nb < 2; ++nb) {
                const int col = nw * 16 + nb * 8 + cc;
                *(float2*)(gp + (size_t)row * Kc + col) =
                    make_float2(acc[ms][nb][0], acc[ms][nb][1]);
                *(float2*)(gp + (size_t)(row + 8) * Kc + col) =
                    make_float2(acc[ms][nb][2], acc[ms][nb][3]);
            }
        }
        __syncthreads();  // ring drained; also orders s_item reuse
#undef LDG_STAGE
#undef STS_STAGE
    }
}

// ---- K2: reduce partials + bias + top-k + softmax (warp per row) ----
__global__ __launch_bounds__(256, 8) void router_topk_kernel(
    const float* __restrict__ b, const int* __restrict__ kptr,
    float* __restrict__ out)
{
    // reset the persistent GEMM's work counter for the next launch/replay
    if (blockIdx.x == 0 && threadIdx.x == 0) g_item = 0;

    const int wid = threadIdx.x >> 5;
    const int lane = threadIdx.x & 31;
    const int row = blockIdx.x * 8 + wid;
    const int c0 = lane * 2;

    float v0 = 0.f, v1 = 0.f;
#pragma unroll
    for (int ks = 0; ks < KSPLIT; ++ks) {
        const float2 p = *(const float2*)(
            g_part + (size_t)ks * NROWS * Kc + (size_t)row * Kc + c0);
        v0 += p.x;
        v1 += p.y;
    }
    v0 = v0 * 0.015625f + b[c0];
    v1 = v1 * 0.015625f + b[c0 + 1];

    int kk = kptr ? *kptr : 2;
    if (kk < 1) kk = 1;
    if (kk > Kc) kk = Kc;

    if (kk == 2) {
        // one-pass top-2 (val desc, idx asc — jax.lax.top_k tie-break)
        float hv, lv;
        int hi_, li_;
        if (v1 > v0) { hv = v1; hi_ = c0 + 1; lv = v0; li_ = c0; }
        else         { hv = v0; hi_ = c0;     lv = v1; li_ = c0 + 1; }
#pragma unroll
        for (int off = 16; off; off >>= 1) {
            const float ohv = __shfl_xor_sync(0xffffffffu, hv, off);
            const float olv = __shfl_xor_sync(0xffffffffu, lv, off);
            const int ohi = __shfl_xor_sync(0xffffffffu, hi_, off);
            const int oli = __shfl_xor_sync(0xffffffffu, li_, off);
            const bool w1_ = (hv > ohv) || (hv == ohv && hi_ < ohi);
            const float whv = w1_ ? hv : ohv;
            const int   whi = w1_ ? hi_ : ohi;
            const float lsv = w1_ ? ohv : hv;
            const int   lsi = w1_ ? ohi : hi_;
            const float wlv = w1_ ? lv : olv;
            const int   wli = w1_ ? li_ : oli;
            const bool sw = (lsv > wlv) || (lsv == wlv && lsi < wli);
            hv = whv; hi_ = whi;
            lv = sw ? lsv : wlv;
            li_ = sw ? lsi : wli;
        }
        const float elo = expf(lv - hv);
        const float inv = 1.0f / (1.0f + elo);
        const float eli = elo * inv;
        const float o0 = (c0 == hi_) ? inv : ((c0 == li_) ? eli : 0.f);
        const float o1 = (c0 + 1 == hi_) ? inv : ((c0 + 1 == li_) ? eli : 0.f);
        *(float2*)(out + (size_t)row * Kc + c0) = make_float2(o0, o1);
        return;
    }

    // generic k path
    unsigned sel = 0;
    float m = 0.f;
    for (int p = 0; p < kk; ++p) {
        float bv = (sel & 1) ? -3.4e38f : v0;
        int bi = c0;
        const float c1v = (sel & 2) ? -3.4e38f : v1;
        if (c1v > bv) { bv = c1v; bi = c0 + 1; }
#pragma unroll
        for (int off = 16; off; off >>= 1) {
            const float ov = __shfl_xor_sync(0xffffffffu, bv, off);
            const int oi = __shfl_xor_sync(0xffffffffu, bi, off);
            if (ov > bv || (ov == bv && oi < bi)) { bv = ov; bi = oi; }
        }
        if (p == 0) m = bv;
        if ((bi >> 1) == lane) sel |= 1u << (bi & 1);
    }
    const float e0 = (sel & 1) ? expf(v0 - m) : 0.f;
    const float e1 = (sel & 2) ? expf(v1 - m) : 0.f;
    float s = e0 + e1;
#pragma unroll
    for (int off = 16; off; off >>= 1) s += __shfl_xor_sync(0xffffffffu, s, off);
    const float inv = 1.0f / s;
    *(float2*)(out + (size_t)row * Kc + c0) = make_float2(e0 * inv, e1 * inv);
}

extern "C" void kernel_launch(void* const* d_in, const int* in_sizes, int n_in,
                              void* d_out, int out_size) {
    const float* z = (const float*)d_in[0];
    const float* W = (const float*)d_in[1];
    const float* b = (const float*)d_in[2];
    const int* kp = (n_in > 3) ? (const int*)d_in[3] : nullptr;
    float* out = (float*)d_out;

    cudaFuncSetAttribute(router_gemm_kernel,
                         cudaFuncAttributeMaxDynamicSharedMemorySize, SMEM1);

    const int N = in_sizes[0] / D;                      // 8192
    router_gemm_kernel<<<GRID1, NT1, SMEM1>>>(z, W);
    router_topk_kernel<<<N / 8, 256>>>(b, kp, out);
    (void)out_size;
}